// round 7
// baseline (speedup 1.0000x reference)
#include <cuda_runtime.h>
#include <cstdint>

#define B_  8
#define N_  2048
#define D_  1024
#define E_  64
#define CAP_ 64
#define TOK_ (B_*N_)                     // 16384
#define DTOT_ ((long long)TOK_*E_*CAP_)  // 67108864

#define GEMMB 512      // GEMM blocks in K1 (32 tokens each)
#define FILLB 1024     // zero-fill blocks in K1 (512KB each)

// -------- scratch (device globals; no allocation allowed) --------
__device__ float d_g1[TOK_], d_g2[TOK_];
__device__ int   d_i1[TOK_], d_i2[TOK_];
__device__ int   d_keep2[TOK_];
__device__ float d_sumg[B_*E_];
__device__ int   d_cnt1[B_*E_];

// -------- packed f32x2 helpers --------
__device__ __forceinline__ unsigned long long pk2(float v) {
    unsigned long long r;
    asm("mov.b64 %0, {%1, %1};" : "=l"(r) : "f"(v));
    return r;
}
__device__ __forceinline__ void fma2(unsigned long long& acc, unsigned long long a,
                                     unsigned long long b) {
    asm("fma.rn.f32x2 %0, %1, %2, %0;" : "+l"(acc) : "l"(a), "l"(b));
}
__device__ __forceinline__ void unpk2(unsigned long long v, float& lo, float& hi) {
    asm("mov.b64 {%0, %1}, %2;" : "=f"(lo), "=f"(hi) : "l"(v));
}

// -------- per-token top2 + softmax + gate output (group of 4 lanes) --------
__device__ __forceinline__ void do_token(float v[16], int g, int b, int tok,
                                         float ls[16]) {
    float m1 = -1e30f, m2 = -1e30f; int i1 = 0, i2 = 0;
#pragma unroll
    for (int j = 0; j < 16; j++) {
        int e = (g << 2) + ((j >> 2) << 4) + (j & 3);
        float val = v[j];
        if (val > m1)      { m2 = m1; i2 = i1; m1 = val; i1 = e; }
        else if (val > m2) { m2 = val; i2 = e; }
    }
#pragma unroll
    for (int d = 1; d <= 2; d <<= 1) {
        float om1 = __shfl_xor_sync(0xffffffffu, m1, d);
        int   oi1 = __shfl_xor_sync(0xffffffffu, i1, d);
        float om2 = __shfl_xor_sync(0xffffffffu, m2, d);
        int   oi2 = __shfl_xor_sync(0xffffffffu, i2, d);
        if (om1 > m1 || (om1 == m1 && oi1 < i1)) {
            float c = m1; int ci = i1;
            m1 = om1; i1 = oi1;
            if (om2 > c || (om2 == c && oi2 < ci)) { m2 = om2; i2 = oi2; }
            else                                   { m2 = c;   i2 = ci;  }
        } else {
            if (om1 > m2 || (om1 == m2 && oi1 < i2)) { m2 = om1; i2 = oi1; }
        }
    }
    float s = 0.0f;
#pragma unroll
    for (int j = 0; j < 16; j++) { v[j] = __expf(v[j] - m1); s += v[j]; }
    s += __shfl_xor_sync(0xffffffffu, s, 1);
    s += __shfl_xor_sync(0xffffffffu, s, 2);
    float invZ = 1.0f / s;
#pragma unroll
    for (int j = 0; j < 16; j++) ls[j] += v[j] * invZ;

    if (g == 0) {
        float e2v = __expf(m2 - m1);
        float den = 1.0f + e2v + 1e-9f * s;
        float g1 = 1.0f / den, g2 = e2v / den;
        d_g1[tok] = g1;  d_g2[tok] = g2;
        d_i1[tok] = i1;  d_i2[tok] = i2;
        d_keep2[tok] = (g2 > 0.2f) ? 1 : 0;
        atomicAdd(&d_cnt1[(b << 6) + i1], 1);
    }
}

// -------- K1: role-split launch: 512 GEMM blocks + 1024 zero-fill blocks ----
// Footprint tuned for occupancy: KC=32 -> 12.4KB smem; launch_bounds(128,9)
// caps regs at 56 so ~9 blocks/SM co-reside (36 warps, vs 24 in R6).
#define TPB1 128
#define KC   32
#define TOKB 32
__global__ __launch_bounds__(TPB1, 9) void k1_gate_fill(const float* __restrict__ x,
                                                        const float* __restrict__ W,
                                                        float* __restrict__ out) {
    const int tid = threadIdx.x;

    if (blockIdx.x >= GEMMB) {
        // ---------------- fill role: stream 512KB of zeros ----------------
        const long long fb = blockIdx.x - GEMMB;
        float4* outv = (float4*)out;
        const long long base = fb * (long long)(TPB1 * 256);
        const float4 z4 = make_float4(0.f, 0.f, 0.f, 0.f);
#pragma unroll 8
        for (int j = 0; j < 256; j++)
            outv[base + tid + (long long)j * TPB1] = z4;
        return;
    }

    // ---------------- GEMM role: 1 token per 4-thread group ----------------
    __shared__ float sx[TOKB][KC + 1];   // 32 x 33 floats = 4.2KB
    __shared__ float sw[KC][E_];         // 32 x 64 floats = 8.2KB

    const int g    = tid & 3;            // expert group: experts g*4 + 16i + s
    const int q    = tid >> 2;           // token index in block 0..31
    const int tok0 = blockIdx.x * TOKB;
    const int tok  = tok0 + q;
    const int b    = tok0 >> 11;

    unsigned long long acc[8];
#pragma unroll
    for (int j = 0; j < 8; j++) acc[j] = 0ULL;

    for (int c = 0; c < D_/KC; c++) {
        const int kc = c * KC;
        // W chunk: KC*E_ = 2048 floats = 512 float4 -> 4 iters (coalesced)
        {
            const float4* wg = (const float4*)(W + kc * E_);
            float4* ws = (float4*)&sw[0][0];
#pragma unroll
            for (int i = 0; i < 4; i++) ws[tid + i*TPB1] = wg[tid + i*TPB1];
        }
        // x chunk: 32 rows x 32 floats = 256 float4 -> 2 iters (ALL rows)
        {
#pragma unroll
            for (int i = 0; i < 2; i++) {
                int f = tid + i*TPB1;
                int r = f >> 3;            // 8 float4 per row -> r in 0..31
                int cc = (f & 7) * 4;
                float4 v = *(const float4*)(x + (size_t)(tok0 + r)*D_ + kc + cc);
                float* dst = &sx[r][cc];
                dst[0]=v.x; dst[1]=v.y; dst[2]=v.z; dst[3]=v.w;
            }
        }
        __syncthreads();

#pragma unroll 4
        for (int kk = 0; kk < KC; kk++) {
            unsigned long long xp = pk2(sx[q][kk]);
            const ulonglong2* wp = (const ulonglong2*)&sw[kk][g*4];
            ulonglong2 w0 = wp[0];    // experts g*4+0..3
            ulonglong2 w1 = wp[4];    // +16 floats
            ulonglong2 w2 = wp[8];    // +32
            ulonglong2 w3 = wp[12];   // +48
            fma2(acc[0], xp, w0.x); fma2(acc[1], xp, w0.y);
            fma2(acc[2], xp, w1.x); fma2(acc[3], xp, w1.y);
            fma2(acc[4], xp, w2.x); fma2(acc[5], xp, w2.y);
            fma2(acc[6], xp, w3.x); fma2(acc[7], xp, w3.y);
        }
        __syncthreads();
    }

    // unpack; v[4i+s] = expert g*4+16i+s  (same mapping as passing R6 kernel)
    float v[16], ls[16];
#pragma unroll
    for (int j = 0; j < 8; j++) unpk2(acc[j], v[2*j], v[2*j+1]);
#pragma unroll
    for (int j = 0; j < 16; j++) ls[j] = 0.0f;

    do_token(v, g, b, tok, ls);

    // loss partial: sum per-expert probs over the warp's 8 tokens
#pragma unroll
    for (int j = 0; j < 16; j++) {
        float t = ls[j];
        t += __shfl_xor_sync(0xffffffffu, t, 4);
        t += __shfl_xor_sync(0xffffffffu, t, 8);
        t += __shfl_xor_sync(0xffffffffu, t, 16);
        if ((tid & 31) < 4) {
            int e = (g << 2) + ((j >> 2) << 4) + (j & 3);
            atomicAdd(&d_sumg[(b << 6) + e], t);
        }
    }
}

// -------- K2: parallel capacity scan + scatter (8 warps per batch) ---------
__global__ __launch_bounds__(256) void k2_scan_scatter(float* __restrict__ out) {
    const int b    = blockIdx.x;
    const int tid  = threadIdx.x;
    const int w    = tid >> 5;
    const int lane = tid & 31;
    const unsigned lt = (1u << lane) - 1u;

    __shared__ int cnt[8][E_];
    __shared__ int pre[8][E_];
    __shared__ int m1c[E_];

    for (int i = tid; i < 8*E_; i += 256) ((int*)cnt)[i] = 0;
    __syncthreads();

    const int base = b * N_ + w * 256;

    // ---- pass 1: top-1 ----
    int i1v[8], lp1[8];
#pragma unroll
    for (int c = 0; c < 8; c++) {
        int t  = base + c*32 + lane;
        int i1 = d_i1[t];
        i1v[c] = i1;
        unsigned grp = __match_any_sync(0xffffffffu, i1);
        int before = __popc(grp & lt);
        int cv = cnt[w][i1];
        __syncwarp();
        lp1[c] = cv + before;
        if (lane == __ffs(grp) - 1) cnt[w][i1] = cv + __popc(grp);
        __syncwarp();
    }
    __syncthreads();

    if (tid < E_) {
        int s = 0;
#pragma unroll
        for (int ww = 0; ww < 8; ww++) { pre[ww][tid] = s; s += cnt[ww][tid]; }
        m1c[tid] = min(s, CAP_);
    }
    __syncthreads();

#pragma unroll
    for (int c = 0; c < 8; c++) {
        int t   = base + c*32 + lane;
        int pos = lp1[c] + pre[w][i1v[c]];
        if (pos < CAP_) {
            long long baseD = (long long)t * (E_*CAP_);
            int o = i1v[c]*CAP_ + pos;
            out[baseD + o]         = 1.0f;
            out[DTOT_ + baseD + o] = d_g1[t];
        }
    }
    __syncthreads();

    // ---- pass 2: top-2 (thresholded), offset by mask_1_count ----
    for (int i = tid; i < 8*E_; i += 256) ((int*)cnt)[i] = 0;
    __syncthreads();

    int i2v[8], lp2[8], kp2[8];
#pragma unroll
    for (int c = 0; c < 8; c++) {
        int t  = base + c*32 + lane;
        int i2 = d_i2[t];
        int kp = d_keep2[t];
        i2v[c] = i2; kp2[c] = kp;
        unsigned km  = __ballot_sync(0xffffffffu, kp);
        unsigned grp = __match_any_sync(0xffffffffu, i2) & km;
        int before = __popc(grp & lt);
        int cv = cnt[w][i2];
        __syncwarp();
        lp2[c] = cv + before;
        if (kp && lane == __ffs(grp) - 1) cnt[w][i2] = cv + __popc(grp);
        __syncwarp();
    }
    __syncthreads();

    if (tid < E_) {
        int s = 0;
#pragma unroll
        for (int ww = 0; ww < 8; ww++) { pre[ww][tid] = s; s += cnt[ww][tid]; }
    }
    __syncthreads();

#pragma unroll
    for (int c = 0; c < 8; c++) {
        if (!kp2[c]) continue;
        int t   = base + c*32 + lane;
        int e   = i2v[c];
        int pos = lp2[c] + pre[w][e] + m1c[e];
        if (pos < CAP_) {
            long long baseD = (long long)t * (E_*CAP_);
            int o = e*CAP_ + pos;
            out[baseD + o]         = 1.0f;
            out[DTOT_ + baseD + o] = d_g2[t];
        }
    }
}

// -------- K4: loss finalize + scratch re-zero for next graph replay --------
__global__ __launch_bounds__(512) void k4_loss(float* __restrict__ out, long long out_size) {
    __shared__ float red[16];
    const int i = threadIdx.x;          // 512 = B_*E_
    float v = d_sumg[i] * (float)d_cnt1[i];
    v += __shfl_xor_sync(0xffffffffu, v, 16);
    v += __shfl_xor_sync(0xffffffffu, v, 8);
    v += __shfl_xor_sync(0xffffffffu, v, 4);
    v += __shfl_xor_sync(0xffffffffu, v, 2);
    v += __shfl_xor_sync(0xffffffffu, v, 1);
    if ((i & 31) == 0) red[i >> 5] = v;
    d_sumg[i] = 0.0f;
    d_cnt1[i] = 0;
    __syncthreads();
    if (i == 0) {
        float s = 0.0f;
        for (int w = 0; w < 16; w++) s += red[w];
        float loss = s * (8.0f / ((float)N_ * (float)N_));
        if (out_size > 2*DTOT_) out[2*DTOT_] = loss;
    }
}

extern "C" void kernel_launch(void* const* d_in, const int* in_sizes, int n_in,
                              void* d_out, int out_size) {
    const float* x = (const float*)d_in[0];
    const float* W = (const float*)d_in[1];
    float* out = (float*)d_out;

    k1_gate_fill<<<GEMMB + FILLB, TPB1>>>(x, W, out);  // 1536 blocks
    k2_scan_scatter<<<B_, 256>>>(out);                 // 8 blocks
    k4_loss<<<1, 512>>>(out, (long long)out_size);
}